// round 1
// baseline (speedup 1.0000x reference)
#include <cuda_runtime.h>
#include <cstdint>

#define K_TOP    30
#define EMB_DIM  128
#define SORT_N   256
#define NTHREADS 256

// Map float -> uint32 whose unsigned order matches float order (ascending).
__device__ __forceinline__ unsigned int float_to_sortable(float f) {
    unsigned int b = __float_as_uint(f);
    return (b & 0x80000000u) ? ~b : (b | 0x80000000u);
}

__global__ void __launch_bounds__(NTHREADS)
sortpool_kernel(const float* __restrict__ emb,
                const int*   __restrict__ sizes,
                float*       __restrict__ out,
                int G) {
    const int g   = blockIdx.x;
    const int tid = threadIdx.x;

    __shared__ unsigned long long s[SORT_N];
    __shared__ int red[NTHREADS];
    __shared__ int sh_off, sh_size;
    __shared__ int tops[K_TOP];

    // ---- offset = prefix sum of sizes[0..g-1] (sizes array is L2-resident) ----
    int acc = 0;
    for (int j = tid; j < g; j += NTHREADS) acc += sizes[j];
    red[tid] = acc;
    __syncthreads();
    #pragma unroll
    for (int st = NTHREADS / 2; st > 0; st >>= 1) {
        if (tid < st) red[tid] += red[tid + st];
        __syncthreads();
    }
    if (tid == 0) { sh_off = red[0]; sh_size = sizes[g]; }
    __syncthreads();
    const int offset = sh_off;
    const int size   = sh_size;

    // ---- build composite sort keys: (sortable(val) << 32) | ~local_idx ----
    // Descending composite order == descending value, ascending index on ties.
    unsigned long long key;
    if (tid < size) {
        float v = emb[(size_t)(offset + tid) * EMB_DIM + (EMB_DIM - 1)];
        key = ((unsigned long long)float_to_sortable(v) << 32)
              | (unsigned int)(~(unsigned int)tid);
    } else {
        // pad: high word 0 < sortable of any finite float (min is 0x00800000)
        key = (unsigned long long)(unsigned int)(~(unsigned int)tid);
    }
    s[tid] = key;
    __syncthreads();

    // ---- bitonic sort, descending ----
    #pragma unroll 1
    for (int k = 2; k <= SORT_N; k <<= 1) {
        #pragma unroll 1
        for (int j = k >> 1; j > 0; j >>= 1) {
            int ixj = tid ^ j;
            if (ixj > tid) {
                unsigned long long a = s[tid], b = s[ixj];
                bool sw = ((tid & k) == 0) ? (a < b) : (a > b);
                if (sw) { s[tid] = b; s[ixj] = a; }
            }
            __syncthreads();
        }
    }

    // ---- emit indices (as float) + record top-K local indices ----
    const int kmax = min(K_TOP, size);
    if (tid < K_TOP) {
        int lidx = (int)(~(unsigned int)(s[tid] & 0xFFFFFFFFull));
        tops[tid] = lidx;
        float idxval = (tid < kmax) ? (float)(offset + lidx) : -1.0f;
        out[(size_t)G * K_TOP * EMB_DIM + (size_t)g * K_TOP + tid] = idxval;
    }
    __syncthreads();

    // ---- gather 30 rows x 128 f32, float4-vectorized ----
    float4*       out4 = (float4*)(out + (size_t)g * K_TOP * EMB_DIM);
    const float4* emb4 = (const float4*)emb;
    const int lane = tid & 31;
    const int wrow = tid >> 5;            // 0..7
    #pragma unroll
    for (int r = wrow; r < K_TOP; r += 8) {
        float4 v;
        if (r < kmax) {
            int node = offset + tops[r];
            v = emb4[(size_t)node * (EMB_DIM / 4) + lane];
        } else {
            v = make_float4(0.f, 0.f, 0.f, 0.f);
        }
        out4[r * (EMB_DIM / 4) + lane] = v;
    }
}

extern "C" void kernel_launch(void* const* d_in, const int* in_sizes, int n_in,
                              void* d_out, int out_size) {
    const float* emb   = (const float*)d_in[0];
    const int*   sizes = (const int*)d_in[1];
    const int G = in_sizes[1];
    sortpool_kernel<<<G, NTHREADS>>>(emb, sizes, (float*)d_out, G);
}

// round 2
// speedup vs baseline: 1.4169x; 1.4169x over previous
#include <cuda_runtime.h>
#include <cstdint>

#define K_TOP    30
#define EMB_DIM  128
#define NT       256

// Map float -> uint32 whose unsigned order matches float order (ascending).
__device__ __forceinline__ unsigned int float_to_sortable(float f) {
    unsigned int b = __float_as_uint(f);
    return (b & 0x80000000u) ? ~b : (b | 0x80000000u);
}

__device__ __forceinline__ unsigned long long shflx64(unsigned long long x, int m) {
    unsigned lo = (unsigned)x, hi = (unsigned)(x >> 32);
    lo = __shfl_xor_sync(0xffffffffu, lo, m);
    hi = __shfl_xor_sync(0xffffffffu, hi, m);
    return ((unsigned long long)hi << 32) | lo;
}

__device__ __forceinline__ unsigned long long cmpx(unsigned long long a,
                                                   unsigned long long b,
                                                   bool keep_max) {
    unsigned long long mx = a > b ? a : b;
    unsigned long long mn = a > b ? b : a;
    return keep_max ? mx : mn;
}

__global__ void __launch_bounds__(NT)
sortpool_kernel(const float* __restrict__ emb,
                const int*   __restrict__ sizes,
                float*       __restrict__ out,
                int G) {
    const int g    = blockIdx.x;
    const int tid  = threadIdx.x;
    const int lane = tid & 31;
    const int wid  = tid >> 5;

    __shared__ unsigned long long s[NT];
    __shared__ int wsum[NT / 32];
    __shared__ int sh_off;
    __shared__ int tops[K_TOP];

    // ---- offset = prefix sum of sizes[0..g-1] (L2-resident, coalesced) ----
    int acc = 0;
    for (int j = tid; j < g; j += NT) acc += sizes[j];
    #pragma unroll
    for (int m = 16; m; m >>= 1) acc += __shfl_xor_sync(0xffffffffu, acc, m);
    if (lane == 0) wsum[wid] = acc;
    __syncthreads();
    if (tid == 0) {
        int o = 0;
        #pragma unroll
        for (int w = 0; w < NT / 32; w++) o += wsum[w];
        sh_off = o;
    }
    __syncthreads();
    const int offset = sh_off;
    const int size   = sizes[g];

    // ---- composite key: (sortable(val) << 32) | ~local_idx ----
    // Descending composite order == descending value, ascending index on ties.
    unsigned long long key;
    if (tid < size) {
        float v = __ldg(&emb[(size_t)(offset + tid) * EMB_DIM + (EMB_DIM - 1)]);
        key = ((unsigned long long)float_to_sortable(v) << 32)
              | (unsigned int)(~(unsigned int)tid);
    } else {
        // pad: high word 0 < sortable encoding of any finite float
        key = (unsigned long long)(unsigned int)(~(unsigned int)tid);
    }

    // ---- bitonic sort (descending), element tid in register ----
    // Stages with partner distance < 32: warp shuffles (no smem, no barriers).
    // Stages with partner distance >= 32: one STS.64 + LDS.64 exchange.

    // k = 2..32 : fully intra-warp
    #pragma unroll
    for (int k = 2; k <= 32; k <<= 1) {
        const bool dir = ((tid & k) == 0);
        #pragma unroll
        for (int j = k >> 1; j >= 1; j >>= 1) {
            bool lower = ((tid & j) == 0);
            unsigned long long other = shflx64(key, j);
            key = cmpx(key, other, lower == dir);
        }
    }

    // k = 64, 128, 256 : cross-warp head stages via smem, tail via shuffles
    #pragma unroll
    for (int k = 64; k <= 256; k <<= 1) {
        const bool dir = ((tid & k) == 0);
        for (int j = k >> 1; j >= 32; j >>= 1) {
            s[tid] = key;
            __syncthreads();
            unsigned long long other = s[tid ^ j];
            bool lower = ((tid & j) == 0);
            key = cmpx(key, other, lower == dir);
            __syncthreads();
        }
        #pragma unroll
        for (int j = 16; j >= 1; j >>= 1) {
            bool lower = ((tid & j) == 0);
            unsigned long long other = shflx64(key, j);
            key = cmpx(key, other, lower == dir);
        }
    }

    // ---- element tid now holds rank-tid key (descending) ----
    const int kmax = min(K_TOP, size);
    if (tid < K_TOP) {
        int lidx = (int)(~(unsigned int)(key & 0xFFFFFFFFull));
        tops[tid] = lidx;
        float idxval = (tid < kmax) ? (float)(offset + lidx) : -1.0f;
        out[(size_t)G * K_TOP * EMB_DIM + (size_t)g * K_TOP + tid] = idxval;
    }
    __syncthreads();

    // ---- gather 30 rows x 128 f32, float4-vectorized, one warp per row ----
    float4*       out4 = (float4*)(out + (size_t)g * K_TOP * EMB_DIM);
    const float4* emb4 = (const float4*)emb;
    #pragma unroll
    for (int r = wid; r < K_TOP; r += NT / 32) {
        float4 v;
        if (r < kmax) {
            int node = offset + tops[r];
            v = __ldg(&emb4[(size_t)node * (EMB_DIM / 4) + lane]);
        } else {
            v = make_float4(0.f, 0.f, 0.f, 0.f);
        }
        out4[r * (EMB_DIM / 4) + lane] = v;
    }
}

extern "C" void kernel_launch(void* const* d_in, const int* in_sizes, int n_in,
                              void* d_out, int out_size) {
    const float* emb   = (const float*)d_in[0];
    const int*   sizes = (const int*)d_in[1];
    const int G = in_sizes[1];
    sortpool_kernel<<<G, NT>>>(emb, sizes, (float*)d_out, G);
}

// round 3
// speedup vs baseline: 1.8310x; 1.2922x over previous
#include <cuda_runtime.h>
#include <cstdint>

#define K_TOP    30
#define EMB_DIM  128
#define NT       256

// Map float -> uint32 whose unsigned order matches float order (ascending).
__device__ __forceinline__ unsigned int float_to_sortable(float f) {
    unsigned int b = __float_as_uint(f);
    return (b & 0x80000000u) ? ~b : (b | 0x80000000u);
}

__device__ __forceinline__ unsigned long long shflx64(unsigned long long x, int m) {
    unsigned lo = (unsigned)x, hi = (unsigned)(x >> 32);
    lo = __shfl_xor_sync(0xffffffffu, lo, m);
    hi = __shfl_xor_sync(0xffffffffu, hi, m);
    return ((unsigned long long)hi << 32) | lo;
}

__device__ __forceinline__ unsigned long long cmpx(unsigned long long a,
                                                   unsigned long long b,
                                                   bool keep_max) {
    unsigned long long mx = a > b ? a : b;
    unsigned long long mn = a > b ? b : a;
    return keep_max ? mx : mn;
}

// 5-stage descending bitonic merge of a bitonic sequence held across the warp.
__device__ __forceinline__ unsigned long long warp_merge_desc(unsigned long long key,
                                                              int lane) {
    #pragma unroll
    for (int j = 16; j >= 1; j >>= 1) {
        bool lower = (lane & j) == 0;
        unsigned long long other = shflx64(key, j);
        key = cmpx(key, other, lower);
    }
    return key;
}

__global__ void __launch_bounds__(NT)
sortpool_kernel(const float* __restrict__ emb,
                const int*   __restrict__ sizes,
                float*       __restrict__ out,
                int G) {
    const int g    = blockIdx.x;
    const int tid  = threadIdx.x;
    const int lane = tid & 31;
    const int wid  = tid >> 5;

    __shared__ unsigned long long s[NT];
    __shared__ int wsum[NT / 32];
    __shared__ int sh_off;
    __shared__ int tops[K_TOP];

    // ---- offset = prefix sum of sizes[0..g-1] (L2-resident, coalesced) ----
    int acc = 0;
    for (int j = tid; j < g; j += NT) acc += sizes[j];
    #pragma unroll
    for (int m = 16; m; m >>= 1) acc += __shfl_xor_sync(0xffffffffu, acc, m);
    if (lane == 0) wsum[wid] = acc;
    __syncthreads();
    if (tid == 0) {
        int o = 0;
        #pragma unroll
        for (int w = 0; w < NT / 32; w++) o += wsum[w];
        sh_off = o;
    }
    __syncthreads();
    const int offset = sh_off;
    const int size   = sizes[g];
    const int nwarps = (size + 31) >> 5;   // warps that hold real data

    unsigned long long key = (unsigned long long)(unsigned int)(~(unsigned int)tid);

    if (wid < nwarps) {
        // ---- composite key: (sortable(val) << 32) | ~local_idx ----
        // Descending composite order == descending value, ascending index on ties.
        if (tid < size) {
            float v = __ldg(&emb[(size_t)(offset + tid) * EMB_DIM + (EMB_DIM - 1)]);
            key = ((unsigned long long)float_to_sortable(v) << 32)
                  | (unsigned int)(~(unsigned int)tid);
        }
        // ---- warp-local descending bitonic sort of 32 keys ----
        #pragma unroll
        for (int k = 2; k <= 16; k <<= 1) {
            const bool dir = ((lane & k) == 0);
            #pragma unroll
            for (int j = k >> 1; j >= 1; j >>= 1) {
                bool lower = (lane & j) == 0;
                unsigned long long other = shflx64(key, j);
                key = cmpx(key, other, lower == dir);
            }
        }
        key = warp_merge_desc(key, lane);   // final k=32 pass, descending
        s[tid] = key;
    }
    __syncthreads();

    // ---- top-32 merge tree over nwarps sorted runs ----
    // Winner wid merges partner (wid+step): top-32 of two descending runs is
    // max(a[lane], b[31-lane]) (bitonic), cleaned by a 5-stage merge.
    // Within a step, writes (winner slots) and reads (partner slots) are disjoint.
    for (int step = 1; step < nwarps; step <<= 1) {
        bool winner = ((wid & (2 * step - 1)) == 0) && (wid + step < nwarps);
        if (winner) {
            unsigned long long other = s[(wid + step) * 32 + (31 - lane)];
            key = key > other ? key : other;
            key = warp_merge_desc(key, lane);
            s[tid] = key;
        }
        __syncthreads();
    }

    // ---- warp 0 lane r holds rank-r key (descending) ----
    const int kmax = min(K_TOP, size);
    if (wid == 0 && lane < K_TOP) {
        int lidx = (int)(~(unsigned int)(key & 0xFFFFFFFFull));
        tops[lane] = lidx;
        float idxval = (lane < kmax) ? (float)(offset + lidx) : -1.0f;
        __stcs(&out[(size_t)G * K_TOP * EMB_DIM + (size_t)g * K_TOP + lane], idxval);
    }
    __syncthreads();

    // ---- gather 30 rows x 128 f32, float4-vectorized, one warp per row ----
    float4*       out4 = (float4*)(out + (size_t)g * K_TOP * EMB_DIM);
    const float4* emb4 = (const float4*)emb;
    #pragma unroll
    for (int r = wid; r < K_TOP; r += NT / 32) {
        float4 v;
        if (r < kmax) {
            int node = offset + tops[r];
            v = __ldg(&emb4[(size_t)node * (EMB_DIM / 4) + lane]);
        } else {
            v = make_float4(0.f, 0.f, 0.f, 0.f);
        }
        __stcs(&out4[r * (EMB_DIM / 4) + lane], v);
    }
}

extern "C" void kernel_launch(void* const* d_in, const int* in_sizes, int n_in,
                              void* d_out, int out_size) {
    const float* emb   = (const float*)d_in[0];
    const int*   sizes = (const int*)d_in[1];
    const int G = in_sizes[1];
    sortpool_kernel<<<G, NT>>>(emb, sizes, (float*)d_out, G);
}